// round 7
// baseline (speedup 1.0000x reference)
#include <cuda_runtime.h>
#include <cstdint>

#define IN_DIM   32768
#define CLASSES  100
#define BATCH    4096
#define NPAD     112
#define SPLITS   4
#define KSPLIT   (IN_DIM / SPLITS)       // 8192
#define KSTAGE   64
#define NITER    (KSPLIT / KSTAGE)       // 128
#define AH_BYTES 8192                    // 128 rows x 64B (s8 hi)
#define AL_BYTES 8192                    // s8 lo
#define BB_BYTES 7168                    // 112 rows x 64B s8
#define STAGE_BYTES (AH_BYTES + AL_BYTES + BB_BYTES)  // 23552
#define STAGES   4
#define THREADS  512

// SW64 swizzle: XOR bits[5:4] with pre-swizzle bits[8:7] (row & 6)
#define SWZ64(o) ((o) ^ (((o) >> 3) & 0x30))

__device__ int8_t g_signB[(size_t)NPAD * IN_DIM];            // 3.7 MB s8 sign(W)
__device__ float  g_partial[(size_t)SPLITS * BATCH * NPAD];  // 7.3 MB split-K partials

// ---------------------------------------------------------------- helpers
__device__ __forceinline__ uint32_t smem_u32(const void* p) {
    uint32_t a;
    asm("{ .reg .u64 t; cvta.to.shared.u64 t, %1; cvt.u32.u64 %0, t; }" : "=r"(a) : "l"(p));
    return a;
}
__device__ __forceinline__ void ldsm_x4(uint32_t& r0, uint32_t& r1, uint32_t& r2, uint32_t& r3,
                                        uint32_t addr) {
    asm volatile("ldmatrix.sync.aligned.m8n8.x4.shared.b16 {%0,%1,%2,%3}, [%4];"
                 : "=r"(r0), "=r"(r1), "=r"(r2), "=r"(r3) : "r"(addr));
}
__device__ __forceinline__ void ldsm_x2(uint32_t& r0, uint32_t& r1, uint32_t addr) {
    asm volatile("ldmatrix.sync.aligned.m8n8.x2.shared.b16 {%0,%1}, [%2];"
                 : "=r"(r0), "=r"(r1) : "r"(addr));
}
__device__ __forceinline__ void mma_s8(int* c, uint32_t a0, uint32_t a1, uint32_t a2,
                                       uint32_t a3, uint32_t b0, uint32_t b1) {
    asm volatile(
        "mma.sync.aligned.m16n8k32.row.col.s32.s8.s8.s32 "
        "{%0,%1,%2,%3}, {%4,%5,%6,%7}, {%8,%9}, {%0,%1,%2,%3};"
        : "+r"(c[0]), "+r"(c[1]), "+r"(c[2]), "+r"(c[3])
        : "r"(a0), "r"(a1), "r"(a2), "r"(a3), "r"(b0), "r"(b1));
}
__device__ __forceinline__ void sts128(uint32_t addr, uint32_t u0, uint32_t u1,
                                       uint32_t u2, uint32_t u3) {
    asm volatile("st.shared.v4.b32 [%0], {%1,%2,%3,%4};"
                 :: "r"(addr), "r"(u0), "r"(u1), "r"(u2), "r"(u3) : "memory");
}
__device__ __forceinline__ void cpasync16(uint32_t saddr, const void* gptr) {
    asm volatile("cp.async.cg.shared.global [%0], [%1], 16;"
                 :: "r"(saddr), "l"(gptr) : "memory");
}

// ---------------------------------------------------------------- kernel 1: sign(W) -> s8
__global__ void sign_kernel(const float* __restrict__ W) {
    int i = blockIdx.x * 256 + threadIdx.x;      // granule = 16 elements
    int n   = i >> 11;                            // 2048 granules per row
    int k16 = i & 2047;
    uint32_t wd[4] = {0u, 0u, 0u, 0u};
    if (n < CLASSES) {
        const float4* p = reinterpret_cast<const float4*>(W + ((size_t)n << 15)) + k16 * 4;
        #pragma unroll
        for (int q = 0; q < 4; q++) {
            float4 f = p[q];
            int s0 = (f.x > 0.f) - (f.x < 0.f);
            int s1 = (f.y > 0.f) - (f.y < 0.f);
            int s2 = (f.z > 0.f) - (f.z < 0.f);
            int s3 = (f.w > 0.f) - (f.w < 0.f);
            wd[q] = (s0 & 255) | ((s1 & 255) << 8) | ((s2 & 255) << 16) | (s3 << 24);
        }
    }
    *reinterpret_cast<uint4*>(g_signB + (size_t)i * 16) =
        make_uint4(wd[0], wd[1], wd[2], wd[3]);
}

// ---------------------------------------------------------------- kernel 2: dual-s8 split-K GEMM
__global__ __launch_bounds__(THREADS, 1)
void binmm_kernel(const float* __restrict__ x) {
    extern __shared__ char smraw[];
    uint32_t sb = (smem_u32(smraw) + 1023u) & ~1023u;

    const int tid  = threadIdx.x;
    const int lane = tid & 31;
    const int w    = tid >> 5;
    const int wm   = w & 7;                      // 8 m-warps (m16 each)
    const int wn   = w >> 3;                     // 2 n-warps (n56 each)
    const int bid  = blockIdx.x;
    const int mtile = bid & 31;
    const int split = bid >> 5;                  // 0..3
    const size_t m0 = (size_t)mtile * 128;
    const int kbase = split * KSPLIT;

    // ---- producer geometry: granule = 16 elems (16B s8 / 64B fp32) ----
    const int prow = tid >> 2;                   // 0..127
    const int pc16 = tid & 3;
    const float* pA = x + (m0 + (size_t)prow) * IN_DIM + kbase + pc16 * 16;
    const uint32_t sAoff = SWZ64((uint32_t)(prow * 64 + pc16 * 16));
    const bool bAct = tid < (NPAD * 4);          // 448 B granules
    const int8_t* pB = g_signB + (size_t)prow * IN_DIM + kbase + pc16 * 16;
    const uint32_t sBoff = sAoff;

    // ---- ldsm base offsets ----
    const int lm = lane >> 3, lr = lane & 7;
    const uint32_t frag = SWZ64((uint32_t)((((lm & 1) ? 8 : 0) + lr) * 64 + (lm >> 1) * 16));
    const uint32_t aOff = frag + (uint32_t)wm * 1024;                 // A: +16 rows per wm
    const uint32_t bOff = frag + (uint32_t)wn * 3584;                 // B: +56 rows per wn
    const uint32_t bX2Off = SWZ64((uint32_t)((48 + lr) * 64 + ((lane >> 3) & 1) * 16))
                            + (uint32_t)wn * 3584;

    int accH[7][4], accL[7][4];
    #pragma unroll
    for (int t = 0; t < 7; t++)
        #pragma unroll
        for (int q = 0; q < 4; q++) { accH[t][q] = 0; accL[t][q] = 0; }

    float4 fa[4];                                // one stage of A in regs (16 floats)

    #define LOADA(it) do {                                                        \
        const float4* _p = reinterpret_cast<const float4*>(pA + (size_t)(it) * KSTAGE); \
        fa[0] = _p[0]; fa[1] = _p[1]; fa[2] = _p[2]; fa[3] = _p[3];               \
    } while (0)

    // convert 16 fp32 -> (hi, lo) s8 planes and store
    #define STSA(soff) do {                                                       \
        uint32_t hw[4], lw[4];                                                    \
        _Pragma("unroll")                                                         \
        for (int q = 0; q < 4; q++) {                                             \
            float4 f = fa[q];                                                     \
            int t0 = __float2int_rn(fmaf(f.x, 4096.f, 128.f));                    \
            int t1 = __float2int_rn(fmaf(f.y, 4096.f, 128.f));                    \
            int t2 = __float2int_rn(fmaf(f.z, 4096.f, 128.f));                    \
            int t3 = __float2int_rn(fmaf(f.w, 4096.f, 128.f));                    \
            uint32_t h01 = __byte_perm(t0, t1, 0x7751);                           \
            uint32_t h23 = __byte_perm(t2, t3, 0x7751);                           \
            hw[q] = __byte_perm(h01, h23, 0x5410);                                \
            uint32_t l01 = __byte_perm(t0, t1, 0x7740);                           \
            uint32_t l23 = __byte_perm(t2, t3, 0x7740);                           \
            lw[q] = __byte_perm(l01, l23, 0x5410) ^ 0x80808080u;                  \
        }                                                                         \
        sts128(sb + (soff) + sAoff, hw[0], hw[1], hw[2], hw[3]);                  \
        sts128(sb + (soff) + AH_BYTES + sAoff, lw[0], lw[1], lw[2], lw[3]);       \
    } while (0)

    #define CPB(it, soff) do {                                                    \
        if (bAct)                                                                 \
            cpasync16(sb + (soff) + AH_BYTES + AL_BYTES + sBoff,                  \
                      pB + (size_t)(it) * KSTAGE);                                \
    } while (0)

    #define COMPUTE(soff) do {                                                    \
        const uint32_t aH = sb + (soff) + aOff;                                   \
        const uint32_t aL = sb + (soff) + AH_BYTES + aOff;                        \
        const uint32_t bB = sb + (soff) + AH_BYTES + AL_BYTES + bOff;             \
        const uint32_t bX = sb + (soff) + AH_BYTES + AL_BYTES + bX2Off;           \
        _Pragma("unroll")                                                         \
        for (int t = 0; t < 2; t++) {                                             \
            const uint32_t kx = 32u * t;                                          \
            uint32_t ah0, ah1, ah2, ah3, al0, al1, al2, al3;                      \
            ldsm_x4(ah0, ah1, ah2, ah3, aH ^ kx);                                 \
            ldsm_x4(al0, al1, al2, al3, aL ^ kx);                                 \
            _Pragma("unroll")                                                     \
            for (int p = 0; p < 3; p++) {                                         \
                uint32_t b0, b1, b2, b3;                                          \
                ldsm_x4(b0, b1, b2, b3, (bB + p * 1024) ^ kx);                    \
                mma_s8(accH[2 * p],     ah0, ah1, ah2, ah3, b0, b2);              \
                mma_s8(accH[2 * p + 1], ah0, ah1, ah2, ah3, b1, b3);              \
                mma_s8(accL[2 * p],     al0, al1, al2, al3, b0, b2);              \
                mma_s8(accL[2 * p + 1], al0, al1, al2, al3, b1, b3);              \
            }                                                                     \
            uint32_t c0, c1;                                                      \
            ldsm_x2(c0, c1, bX ^ kx);                                             \
            mma_s8(accH[6], ah0, ah1, ah2, ah3, c0, c1);                          \
            mma_s8(accL[6], al0, al1, al2, al3, c0, c1);                          \
        }                                                                         \
    } while (0)

    // ---- prologue: fill stages 0..2, hold A(3) in regs ----
    #pragma unroll
    for (int p = 0; p < 3; p++) {
        LOADA(p); STSA((uint32_t)p * STAGE_BYTES); CPB(p, (uint32_t)p * STAGE_BYTES);
        asm volatile("cp.async.commit_group;" ::: "memory");
    }
    LOADA(3);

    // ---- mainloop ----
    for (int i = 0; i < NITER; i++) {
        asm volatile("cp.async.wait_group 2;" ::: "memory");
        __syncthreads();

        const uint32_t soff  = (uint32_t)(i & 3) * STAGE_BYTES;
        const uint32_t soff3 = (uint32_t)((i + 3) & 3) * STAGE_BYTES;

        if (i + 3 < NITER) {
            CPB(i + 3, soff3);
            STSA(soff3);                          // fa currently holds A(i+3)
        }
        asm volatile("cp.async.commit_group;" ::: "memory");
        if (i + 4 < NITER) LOADA(i + 4);

        COMPUTE(soff);
    }

    // ---- epilogue: exact combine 256*hi + lo, store fp32 partials ----
    const int mrow = (int)m0 + 16 * wm + (lane >> 2);
    #pragma unroll
    for (int nt = 0; nt < 7; nt++) {
        int n = 56 * wn + 8 * nt + (lane & 3) * 2;
        size_t idx = ((size_t)split * BATCH + mrow) * NPAD + n;
        int v0 = accH[nt][0] * 256 + accL[nt][0];
        int v1 = accH[nt][1] * 256 + accL[nt][1];
        int v2 = accH[nt][2] * 256 + accL[nt][2];
        int v3 = accH[nt][3] * 256 + accL[nt][3];
        *reinterpret_cast<float2*>(&g_partial[idx]) = make_float2((float)v0, (float)v1);
        *reinterpret_cast<float2*>(&g_partial[idx + 8 * NPAD]) = make_float2((float)v2, (float)v3);
    }
    #undef LOADA
    #undef STSA
    #undef CPB
    #undef COMPUTE
}

// ---------------------------------------------------------------- kernel 3: split-K reduce
__global__ void reduce_kernel(float* __restrict__ out) {
    int idx = blockIdx.x * 256 + threadIdx.x;   // BATCH * CLASSES
    int m = idx / CLASSES;
    int n = idx - m * CLASSES;
    const float scale = 1.3486993476610254e-06f; // 1/(4096*sqrt(32768))
    float a = 0.f;
    #pragma unroll
    for (int s = 0; s < SPLITS; s++)
        a += g_partial[((size_t)s * BATCH + m) * NPAD + n];
    out[idx] = a * scale;
}

// ---------------------------------------------------------------- launch
extern "C" void kernel_launch(void* const* d_in, const int* in_sizes, int n_in,
                              void* d_out, int out_size) {
    const float* x = (const float*)d_in[0];
    const float* W = (const float*)d_in[1];
    float* out = (float*)d_out;

    const int SMEM_DYN = STAGES * STAGE_BYTES + 1024;   // 95232
    cudaFuncSetAttribute(binmm_kernel, cudaFuncAttributeMaxDynamicSharedMemorySize, SMEM_DYN);

    sign_kernel<<<(NPAD * IN_DIM / 16) / 256, 256>>>(W);
    binmm_kernel<<<SPLITS * 32, THREADS, SMEM_DYN>>>(x);
    reduce_kernel<<<(BATCH * CLASSES) / 256, 256>>>(out);
}

// round 10
// speedup vs baseline: 2.7006x; 2.7006x over previous
#include <cuda_runtime.h>
#include <cuda_fp16.h>
#include <cstdint>

#define IN_DIM   32768
#define CLASSES  100
#define BATCH    4096
#define NPAD     112
#define SPLITS   4
#define KSPLIT   (IN_DIM / SPLITS)       // 8192
#define KSTAGE   64
#define NITER    (KSPLIT / KSTAGE)       // 128
#define ABYTES   16384                   // 128 rows x 128B fp16
#define BBYTES   14336                   // 112 rows x 128B fp16
#define STAGE_BYTES (ABYTES + BBYTES)    // 30720
#define STAGES   6
#define THREADS  640                     // 16 consumer warps + 4 producer warps
#define CONS_THR 512

#define SWZ(o) ((o) ^ (((o) >> 3) & 0x70))

__device__ __half g_signW[(size_t)NPAD * IN_DIM];            // 7.3 MB fp16 sign(W)
__device__ float  g_partial[(size_t)SPLITS * BATCH * NPAD];  // 7.3 MB split-K partials

// ---------------------------------------------------------------- helpers
__device__ __forceinline__ uint32_t smem_u32(const void* p) {
    uint32_t a;
    asm("{ .reg .u64 t; cvta.to.shared.u64 t, %1; cvt.u32.u64 %0, t; }" : "=r"(a) : "l"(p));
    return a;
}
__device__ __forceinline__ void ldsm_x4(uint32_t& r0, uint32_t& r1, uint32_t& r2, uint32_t& r3,
                                        uint32_t addr) {
    asm volatile("ldmatrix.sync.aligned.m8n8.x4.shared.b16 {%0,%1,%2,%3}, [%4];"
                 : "=r"(r0), "=r"(r1), "=r"(r2), "=r"(r3) : "r"(addr));
}
__device__ __forceinline__ void ldsm_x2(uint32_t& r0, uint32_t& r1, uint32_t addr) {
    asm volatile("ldmatrix.sync.aligned.m8n8.x2.shared.b16 {%0,%1}, [%2];"
                 : "=r"(r0), "=r"(r1) : "r"(addr));
}
__device__ __forceinline__ void mma16816(float* c, uint32_t a0, uint32_t a1, uint32_t a2,
                                         uint32_t a3, uint32_t b0, uint32_t b1) {
    asm volatile(
        "mma.sync.aligned.m16n8k16.row.col.f32.f16.f16.f32 "
        "{%0,%1,%2,%3}, {%4,%5,%6,%7}, {%8,%9}, {%0,%1,%2,%3};"
        : "+f"(c[0]), "+f"(c[1]), "+f"(c[2]), "+f"(c[3])
        : "r"(a0), "r"(a1), "r"(a2), "r"(a3), "r"(b0), "r"(b1));
}
__device__ __forceinline__ void sts128(uint32_t addr, uint32_t u0, uint32_t u1,
                                       uint32_t u2, uint32_t u3) {
    asm volatile("st.shared.v4.b32 [%0], {%1,%2,%3,%4};"
                 :: "r"(addr), "r"(u0), "r"(u1), "r"(u2), "r"(u3) : "memory");
}
__device__ __forceinline__ void cpasync16(uint32_t saddr, const void* gptr) {
    asm volatile("cp.async.cg.shared.global [%0], [%1], 16;"
                 :: "r"(saddr), "l"(gptr) : "memory");
}
__device__ __forceinline__ uint32_t packh2(float lo, float hi) {
    __half2 h = __floats2half2_rn(lo, hi);
    return *reinterpret_cast<uint32_t*>(&h);
}
__device__ __forceinline__ void mbar_init(uint32_t a, uint32_t cnt) {
    asm volatile("mbarrier.init.shared.b64 [%0], %1;" :: "r"(a), "r"(cnt) : "memory");
}
__device__ __forceinline__ void mbar_arrive(uint32_t a) {
    asm volatile("mbarrier.arrive.shared.b64 _, [%0];" :: "r"(a) : "memory");
}
__device__ __forceinline__ void mbar_wait(uint32_t a, uint32_t ph) {
    asm volatile(
        "{\n\t.reg .pred P;\n\t"
        "LW%=:\n\t"
        "mbarrier.try_wait.parity.acquire.cta.shared::cta.b64 P, [%0], %1, 0x989680;\n\t"
        "@!P bra LW%=;\n\t}"
        :: "r"(a), "r"(ph) : "memory");
}
__device__ __forceinline__ void cpasync_mbar_arrive(uint32_t a) {
    asm volatile("cp.async.mbarrier.arrive.noinc.shared.b64 [%0];" :: "r"(a) : "memory");
}

// ---------------------------------------------------------------- kernel 1: sign(W) -> fp16
__global__ void sign_kernel(const float* __restrict__ W) {
    int i = blockIdx.x * 256 + threadIdx.x;      // granule = 8 elements
    int n  = i >> 12;
    int k8 = i & 4095;
    __half2 h[4];
    if (n < CLASSES) {
        const float4* p = reinterpret_cast<const float4*>(W + ((size_t)n << 15)) + k8 * 2;
        float4 f0 = p[0], f1 = p[1];
        #define SG(v) ((v) > 0.f ? 1.f : ((v) < 0.f ? -1.f : 0.f))
        h[0] = __floats2half2_rn(SG(f0.x), SG(f0.y));
        h[1] = __floats2half2_rn(SG(f0.z), SG(f0.w));
        h[2] = __floats2half2_rn(SG(f1.x), SG(f1.y));
        h[3] = __floats2half2_rn(SG(f1.z), SG(f1.w));
        #undef SG
    } else {
        h[0] = h[1] = h[2] = h[3] = __floats2half2_rn(0.f, 0.f);
    }
    *reinterpret_cast<float4*>(g_signW + (size_t)i * 8) = *reinterpret_cast<float4*>(h);
}

// ---------------------------------------------------------------- kernel 2: warp-specialized GEMM
__global__ __launch_bounds__(THREADS, 1)
void binmm_kernel(const float* __restrict__ x) {
    extern __shared__ char smraw[];
    uint32_t sb  = (smem_u32(smraw) + 1023u) & ~1023u;
    uint32_t bar = sb + STAGES * STAGE_BYTES;    // full[s]=bar+16s, empty[s]=bar+16s+8

    const int tid  = threadIdx.x;
    const int lane = tid & 31;
    const int w    = tid >> 5;
    const int bid  = blockIdx.x;
    const int mtile = bid & 31;
    const int split = bid >> 5;                  // 0..3
    const size_t m0 = (size_t)mtile * 128;
    const int kbase = split * KSPLIT;

    if (tid == 0) {
        #pragma unroll
        for (int s = 0; s < STAGES; s++) {
            mbar_init(bar + 16 * s, 256);        // full: 128 STS arrivals + 128 cp.async arrivals
            mbar_init(bar + 16 * s + 8, 16);     // empty: 16 consumer warps
        }
        asm volatile("fence.proxy.async.shared::cta;" ::: "memory");
    }
    __syncthreads();

    if (tid >= CONS_THR) {
        // ================= PRODUCER (warps 16..19, 128 threads) =================
        const int pt = tid - CONS_THR;           // 0..127
        const float* pA0 = x + (m0 + (size_t)(pt >> 3)) * IN_DIM + kbase + (pt & 7) * 8;
        const __half* pB0 = g_signW + (size_t)(pt >> 3) * IN_DIM + kbase + (pt & 7) * 8;
        const uint32_t sw0 = SWZ((uint32_t)(pt * 16));

        int s = 0, wrap = 0;
        for (int i = 0; i < NITER; i++) {
            const uint32_t soff = (uint32_t)s * STAGE_BYTES;
            if (wrap >= 1) mbar_wait(bar + 16 * s + 8, (wrap - 1) & 1);

            const int koff = i * KSTAGE;
            // A: 8 granules (rows pt>>3 + 16j), in 2 batches of 4
            #pragma unroll
            for (int jb = 0; jb < 2; jb++) {
                float4 u[4], v[4];
                #pragma unroll
                for (int j2 = 0; j2 < 4; j2++) {
                    const float* p = pA0 + (size_t)(jb * 4 + j2) * 16 * IN_DIM + koff;
                    u[j2] = *reinterpret_cast<const float4*>(p);
                    v[j2] = *reinterpret_cast<const float4*>(p + 4);
                }
                #pragma unroll
                for (int j2 = 0; j2 < 4; j2++) {
                    int j = jb * 4 + j2;
                    sts128(sb + soff + sw0 + 2048u * j,
                           packh2(u[j2].x, u[j2].y), packh2(u[j2].z, u[j2].w),
                           packh2(v[j2].x, v[j2].y), packh2(v[j2].z, v[j2].w));
                }
            }
            // B: 7 granules via cp.async (rows pt>>3 + 16j < 112)
            #pragma unroll
            for (int j = 0; j < 7; j++)
                cpasync16(sb + soff + ABYTES + sw0 + 2048u * j,
                          pB0 + (size_t)j * 16 * IN_DIM + koff);

            cpasync_mbar_arrive(bar + 16 * s);   // fires when this thread's cp.asyncs land
            mbar_arrive(bar + 16 * s);           // release: STS A visible

            if (++s == STAGES) { s = 0; wrap++; }
        }
    } else {
        // ================= CONSUMER (warps 0..15) =================
        const int wm = w & 7;                    // m-warp: rows 16*wm..+15
        const int wn = w >> 3;                   // n-warp: cols 56*wn..+55
        const int lm = lane >> 3, lr = lane & 7;
        const uint32_t aOff = SWZ((uint32_t)((16 * wm + ((lm & 1) ? 8 : 0) + lr) * 128
                                             + (lm >> 1) * 16));
        const uint32_t bOff = SWZ((uint32_t)((((lm & 1) ? 8 : 0) + lr) * 128
                                             + (lm >> 1) * 16)) + (uint32_t)wn * 7168;
        const uint32_t bX2  = SWZ((uint32_t)((48 + (lane & 7)) * 128 + ((lane >> 3) & 1) * 16))
                              + (uint32_t)wn * 7168;

        float acc[7][4];
        #pragma unroll
        for (int t = 0; t < 7; t++)
            #pragma unroll
            for (int q = 0; q < 4; q++) acc[t][q] = 0.f;

        int s = 0;
        uint32_t ph = 0;
        for (int i = 0; i < NITER; i++) {
            mbar_wait(bar + 16 * s, ph);         // acquire full[s]
            const uint32_t soff = (uint32_t)s * STAGE_BYTES;
            const uint32_t aA = sb + soff + aOff;
            const uint32_t bA = sb + soff + ABYTES + bOff;
            const uint32_t bX = sb + soff + ABYTES + bX2;

            #pragma unroll
            for (int t = 0; t < 4; t++) {
                const uint32_t kx = 32u * t;
                uint32_t a0, a1, a2, a3;
                ldsm_x4(a0, a1, a2, a3, aA ^ kx);
                #pragma unroll
                for (int p = 0; p < 3; p++) {
                    uint32_t b0, b1, b2, b3;
                    ldsm_x4(b0, b1, b2, b3, (bA + p * 2048) ^ kx);
                    mma16816(acc[2 * p],     a0, a1, a2, a3, b0, b2);
                    mma16816(acc[2 * p + 1], a0, a1, a2, a3, b1, b3);
                }
                uint32_t c0, c1;
                ldsm_x2(c0, c1, bX ^ kx);
                mma16816(acc[6], a0, a1, a2, a3, c0, c1);
            }

            if (lane == 0) mbar_arrive(bar + 16 * s + 8);  // release empty[s]
            if (++s == STAGES) { s = 0; ph ^= 1; }
        }

        // ---- epilogue: split-K partials ----
        const int mrow = (int)m0 + 16 * wm + (lane >> 2);
        #pragma unroll
        for (int nt = 0; nt < 7; nt++) {
            int n = 56 * wn + 8 * nt + (lane & 3) * 2;
            size_t idx = ((size_t)split * BATCH + mrow) * NPAD + n;
            *reinterpret_cast<float2*>(&g_partial[idx]) = make_float2(acc[nt][0], acc[nt][1]);
            *reinterpret_cast<float2*>(&g_partial[idx + 8 * NPAD]) =
                make_float2(acc[nt][2], acc[nt][3]);
        }
    }
}

// ---------------------------------------------------------------- kernel 3: split-K reduce
__global__ void reduce_kernel(float* __restrict__ out) {
    int idx = blockIdx.x * 256 + threadIdx.x;   // BATCH * CLASSES
    int m = idx / CLASSES;
    int n = idx - m * CLASSES;
    const float scale = 0.0055242717280199026f; // 1/sqrt(32768)
    float a = 0.f;
    #pragma unroll
    for (int s = 0; s < SPLITS; s++)
        a += g_partial[((size_t)s * BATCH + m) * NPAD + n];
    out[idx] = a * scale;
}

// ---------------------------------------------------------------- launch
extern "C" void kernel_launch(void* const* d_in, const int* in_sizes, int n_in,
                              void* d_out, int out_size) {
    const float* x = (const float*)d_in[0];
    const float* W = (const float*)d_in[1];
    float* out = (float*)d_out;

    const int SMEM_DYN = STAGES * STAGE_BYTES + 1024 + 256;  // ~185.6 KB
    cudaFuncSetAttribute(binmm_kernel, cudaFuncAttributeMaxDynamicSharedMemorySize, SMEM_DYN);

    sign_kernel<<<(NPAD * IN_DIM / 8) / 256, 256>>>(W);
    binmm_kernel<<<SPLITS * 32, THREADS, SMEM_DYN>>>(x);
    reduce_kernel<<<(BATCH * CLASSES) / 256, 256>>>(out);
}